// round 8
// baseline (speedup 1.0000x reference)
#include <cuda_runtime.h>

#define NN 50000
#define NE 800000
#define NDIM 128
#define HID 64
#define EDIM 16

// ---------------- scratch (device globals; no allocation allowed) ----------
__device__ __align__(16) float g_Hn[NN * HID];     // (X@W) * dinv[row]
__device__ __align__(16) float g_h[NN * HID];      // post relu features
__device__ __align__(16) float g_AB[NN * 128];     // [A | B] per node for edge MLP
__device__ int   g_deg[NN];      // 1 + in-degree
__device__ float g_dinv[NN];
__device__ int   g_offs[NN];     // CSR row offsets (incoming edges)
__device__ int   g_cursor[NN];   // fill cursors
__device__ int   g_csr[NE];      // incoming source list per dst

// ---------------- degree kernels -------------------------------------------
__global__ void k_deg_init(int* deg) {
    int i = blockIdx.x * blockDim.x + threadIdx.x;
    if (i < NN) deg[i] = 1;   // self-loop
}
__global__ void k_deg_count(const int* __restrict__ ei, int* deg) {
    int e = blockIdx.x * blockDim.x + threadIdx.x;
    if (e < NE) atomicAdd(&deg[ei[NE + e]], 1);
}
__global__ void k_deg_inv(const int* __restrict__ deg, float* dinv) {
    int i = blockIdx.x * blockDim.x + threadIdx.x;
    if (i < NN) dinv[i] = rsqrtf((float)deg[i]);
}

// ---------------- CSR build -------------------------------------------------
// Single-block exclusive scan of (deg-1) over 50k nodes.
__global__ void k_scan(const int* __restrict__ deg, int* __restrict__ offs,
                       int* __restrict__ cursor) {
    __shared__ int s[1024];
    int t = threadIdx.x;
    const int C = 49;                       // 49*1024 = 50176 >= NN
    int b = t * C;
    int sum = 0;
    for (int i = 0; i < C; i++) {
        int idx = b + i;
        if (idx < NN) sum += deg[idx] - 1;
    }
    s[t] = sum;
    __syncthreads();
    // Hillis-Steele inclusive scan
    for (int off = 1; off < 1024; off <<= 1) {
        int v = (t >= off) ? s[t - off] : 0;
        __syncthreads();
        s[t] += v;
        __syncthreads();
    }
    int prefix = (t == 0) ? 0 : s[t - 1];
    for (int i = 0; i < C; i++) {
        int idx = b + i;
        if (idx < NN) {
            offs[idx] = prefix;
            cursor[idx] = prefix;
            prefix += deg[idx] - 1;
        }
    }
}

__global__ void k_fill(const int* __restrict__ ei, int* cursor, int* __restrict__ csr) {
    int e = blockIdx.x * blockDim.x + threadIdx.x;
    if (e >= NE) return;
    int src = ei[e];
    int dst = ei[NE + e];
    int pos = atomicAdd(&cursor[dst], 1);
    csr[pos] = src;
}

// ---------------- GEMM: Out[N, 64-col-block] = X[N,K] @ W[K,64] ------------
// block: 64 rows x 64 cols, 256 threads, 4x4 microtile, K chunked by 32.
// If SCALE, rows are multiplied by dinv[row] in the epilogue.
template <int K, bool SCALE>
__global__ void k_gemm64(const float* __restrict__ X, const float* __restrict__ W,
                         const float* __restrict__ dinv,
                         float* __restrict__ Out, int ldout, int colOff) {
    __shared__ float sX[32][65];   // [k][row], padded
    __shared__ float sW[32][64];   // [k][col]
    int t  = threadIdx.x;
    int br = blockIdx.x * 64;
    int tx = t & 15, ty = t >> 4;
    float acc[4][4] = {};

    for (int kc = 0; kc < K; kc += 32) {
        #pragma unroll
        for (int i = 0; i < 8; i++) {
            int e2 = t + i * 256;
            int r = e2 >> 5, kk = e2 & 31;
            int row = br + r;
            sX[kk][r] = (row < NN) ? X[row * K + kc + kk] : 0.f;
        }
        #pragma unroll
        for (int i = 0; i < 8; i++) {
            int e2 = t + i * 256;
            int c = e2 & 63, kk = e2 >> 6;
            sW[kk][c] = W[(kc + kk) * 64 + c];
        }
        __syncthreads();
        #pragma unroll
        for (int kk = 0; kk < 32; kk++) {
            float a[4], b[4];
            #pragma unroll
            for (int i2 = 0; i2 < 4; i2++) a[i2] = sX[kk][ty * 4 + i2];
            #pragma unroll
            for (int j = 0; j < 4; j++) b[j] = sW[kk][tx * 4 + j];
            #pragma unroll
            for (int i2 = 0; i2 < 4; i2++)
                #pragma unroll
                for (int j = 0; j < 4; j++)
                    acc[i2][j] += a[i2] * b[j];
        }
        __syncthreads();
    }
    #pragma unroll
    for (int i2 = 0; i2 < 4; i2++) {
        int row = br + ty * 4 + i2;
        if (row < NN) {
            float sc = SCALE ? dinv[row] : 1.f;
            float4 v = make_float4(acc[i2][0] * sc, acc[i2][1] * sc,
                                   acc[i2][2] * sc, acc[i2][3] * sc);
            *(float4*)&Out[row * ldout + colOff + tx * 4] = v;
        }
    }
}

// ---------------- CSR aggregate: h[d] = relu(dinv[d]*(sum Hn[s] + Hn[d]) + b)
// One warp per node; each lane owns 2 columns (float2).
__global__ void k_aggregate(const float* __restrict__ Hn, const int* __restrict__ csr,
                            const int* __restrict__ offs, const int* __restrict__ deg,
                            const float* __restrict__ dinv, const float* __restrict__ bias,
                            float* __restrict__ hout) {
    int warp = (blockIdx.x * blockDim.x + threadIdx.x) >> 5;
    if (warp >= NN) return;
    int l = threadIdx.x & 31;
    int beg = offs[warp];
    int cnt = deg[warp] - 1;

    // self term
    float2 acc = *(const float2*)&Hn[warp * HID + l * 2];

    int i = 0;
    for (; i + 2 <= cnt; i += 2) {
        int s0 = csr[beg + i];
        int s1 = csr[beg + i + 1];
        float2 v0 = *(const float2*)&Hn[s0 * HID + l * 2];
        float2 v1 = *(const float2*)&Hn[s1 * HID + l * 2];
        acc.x += v0.x + v1.x;
        acc.y += v0.y + v1.y;
    }
    if (i < cnt) {
        int s0 = csr[beg + i];
        float2 v0 = *(const float2*)&Hn[s0 * HID + l * 2];
        acc.x += v0.x;
        acc.y += v0.y;
    }

    float d = dinv[warp];
    float bx = bias[l * 2], by = bias[l * 2 + 1];
    float2 r;
    r.x = fmaxf(acc.x * d + bx, 0.f);
    r.y = fmaxf(acc.y * d + by, 0.f);
    *(float2*)&hout[warp * HID + l * 2] = r;
}

// ---------------- edge MLP: warp per edge ----------------------------------
__global__ void k_edge_mlp(const float* __restrict__ AB, const int* __restrict__ ei,
                           const float* __restrict__ attr, const float* __restrict__ Wm1,
                           const float* __restrict__ bm1, const float* __restrict__ Wm2,
                           const float* __restrict__ bm2, float* __restrict__ out) {
    __shared__ float sWe[EDIM][HID];   // Wm1 rows 128..143
    __shared__ float sW2[HID][2];
    __shared__ float sb1[HID];
    __shared__ float sb2[2];
    int t = threadIdx.x;
    const float* We = Wm1 + 128 * HID;
    for (int i = t; i < EDIM * HID; i += blockDim.x) ((float*)sWe)[i] = We[i];
    for (int i = t; i < HID * 2; i += blockDim.x)    ((float*)sW2)[i] = Wm2[i];
    if (t < HID) sb1[t] = bm1[t];
    if (t < 2)   sb2[t] = bm2[t];
    __syncthreads();

    int e = blockIdx.x * (blockDim.x >> 5) + (t >> 5);
    if (e >= NE) return;
    int l = t & 31;
    int src = ei[e];
    int dst = ei[NE + e];

    float a0 = AB[src * 128 + l];
    float a1 = AB[src * 128 + 32 + l];
    float b0 = AB[dst * 128 + 64 + l];
    float b1 = AB[dst * 128 + 96 + l];

    float av = (l < 16) ? attr[e * EDIM + l] : 0.f;
    float s0 = 0.f, s1 = 0.f;
    #pragma unroll
    for (int k = 0; k < EDIM; k++) {
        float ak = __shfl_sync(0xffffffffu, av, k);
        s0 += ak * sWe[k][l];
        s1 += ak * sWe[k][l + 32];
    }
    float e0 = fmaxf(a0 + b0 + s0 + sb1[l], 0.f);
    float e1 = fmaxf(a1 + b1 + s1 + sb1[l + 32], 0.f);

    float p0 = e0 * sW2[l][0] + e1 * sW2[l + 32][0];
    float p1 = e0 * sW2[l][1] + e1 * sW2[l + 32][1];
    #pragma unroll
    for (int off = 16; off; off >>= 1) {
        p0 += __shfl_xor_sync(0xffffffffu, p0, off);
        p1 += __shfl_xor_sync(0xffffffffu, p1, off);
    }
    if (l == 0) {
        out[e * 2]     = p0 + sb2[0];
        out[e * 2 + 1] = p1 + sb2[1];
    }
}

// ---------------- launch ----------------------------------------------------
extern "C" void kernel_launch(void* const* d_in, const int* in_sizes, int n_in,
                              void* d_out, int out_size) {
    const float* x    = (const float*)d_in[0];
    const int*   ei   = (const int*)d_in[1];     // edge_index is int32 (JAX x64 off)
    const float* attr = (const float*)d_in[2];
    const float* W1   = (const float*)d_in[3];
    const float* b1   = (const float*)d_in[4];
    const float* W2   = (const float*)d_in[5];
    const float* b2   = (const float*)d_in[6];
    const float* Wm1  = (const float*)d_in[7];
    const float* bm1  = (const float*)d_in[8];
    const float* Wm2  = (const float*)d_in[9];
    const float* bm2  = (const float*)d_in[10];
    float* out = (float*)d_out;

    float *Hn, *h, *AB, *dinv; int *deg, *offs, *cursor, *csr;
    cudaGetSymbolAddress((void**)&Hn,     g_Hn);
    cudaGetSymbolAddress((void**)&h,      g_h);
    cudaGetSymbolAddress((void**)&AB,     g_AB);
    cudaGetSymbolAddress((void**)&deg,    g_deg);
    cudaGetSymbolAddress((void**)&dinv,   g_dinv);
    cudaGetSymbolAddress((void**)&offs,   g_offs);
    cudaGetSymbolAddress((void**)&cursor, g_cursor);
    cudaGetSymbolAddress((void**)&csr,    g_csr);

    const int T = 256;
    int gb_nodes = (NN + T - 1) / T;
    int gb_edges = (NE + T - 1) / T;
    int gb_gemm  = (NN + 63) / 64;
    int gb_agg   = (NN * 32 + T - 1) / T;
    int gb_emlp  = (NE + 7) / 8;

    // graph structure (recomputed every call; deterministic)
    k_deg_init<<<gb_nodes, T>>>(deg);
    k_deg_count<<<gb_edges, T>>>(ei, deg);
    k_deg_inv<<<gb_nodes, T>>>(deg, dinv);
    k_scan<<<1, 1024>>>(deg, offs, cursor);
    k_fill<<<gb_edges, T>>>(ei, cursor, csr);

    // ---- GCN layer 1 ----
    k_gemm64<NDIM, true><<<gb_gemm, T>>>(x, W1, dinv, Hn, HID, 0);
    k_aggregate<<<gb_agg, T>>>(Hn, csr, offs, deg, dinv, b1, h);

    // ---- GCN layer 2 ----
    k_gemm64<HID, true><<<gb_gemm, T>>>(h, W2, dinv, Hn, HID, 0);
    k_aggregate<<<gb_agg, T>>>(Hn, csr, offs, deg, dinv, b2, h);

    // ---- per-node edge-MLP partials: A = h2@Wm1[0:64], B = h2@Wm1[64:128] ----
    k_gemm64<HID, false><<<gb_gemm, T>>>(h, Wm1,           nullptr, AB, 128, 0);
    k_gemm64<HID, false><<<gb_gemm, T>>>(h, Wm1 + 64 * 64, nullptr, AB, 128, 64);

    // ---- edge MLP ----
    k_edge_mlp<<<gb_emlp, T>>>(AB, ei, attr, Wm1, bm1, Wm2, bm2, out);
}

// round 9
// speedup vs baseline: 2.1026x; 2.1026x over previous
#include <cuda_runtime.h>

#define NN 50000
#define NE 800000
#define NDIM 128
#define HID 64
#define EDIM 16

// ---------------- scratch (device globals; no allocation allowed) ----------
__device__ __align__(16) float g_Hn[NN * HID];     // (X@W) * dinv[row]
__device__ __align__(16) float g_Acc[NN * HID];    // aggregation accumulator
__device__ __align__(16) float g_AB[NN * 128];     // [A | B] per node for edge MLP
__device__ int   g_deg[NN];
__device__ float g_dinv[NN];

// ---------------- vector reduction helper ----------------------------------
__device__ __forceinline__ void red_add_v4(float* p, float4 v) {
    asm volatile("red.global.add.v4.f32 [%0], {%1,%2,%3,%4};"
                 :: "l"(p), "f"(v.x), "f"(v.y), "f"(v.z), "f"(v.w)
                 : "memory");
}

// ---------------- degree kernels -------------------------------------------
__global__ void k_deg_init(int* deg) {
    int i = blockIdx.x * blockDim.x + threadIdx.x;
    if (i < NN) deg[i] = 1;   // self-loop
}
__global__ void k_deg_count(const int* __restrict__ ei, int* deg) {
    int e = blockIdx.x * blockDim.x + threadIdx.x;
    if (e < NE) atomicAdd(&deg[ei[NE + e]], 1);
}
__global__ void k_deg_inv(const int* __restrict__ deg, float* dinv) {
    int i = blockIdx.x * blockDim.x + threadIdx.x;
    if (i < NN) dinv[i] = rsqrtf((float)deg[i]);
}

// ---------------- GEMM: Out = [relu(X+b)] @ W[K,64] ------------------------
// 64x64 tile, 256 threads, 4x4 microtile.
// IN_RELU: input rows pass through relu(x + inb[col]) while staging to smem.
// OUT_NORM: write Hn = acc*dinv[row] and Acc = Hn*dinv[row] (self-loop init).
// else:     write acc to OutA[row*ldA + colOff + ...].
template <int K, bool IN_RELU, bool OUT_NORM>
__global__ void k_gemm64(const float* __restrict__ X, const float* __restrict__ W,
                         const float* __restrict__ inb, const float* __restrict__ dinv,
                         float* __restrict__ OutA, float* __restrict__ OutB,
                         int ldA, int colOff) {
    __shared__ float sX[32][65];   // [k][row], padded
    __shared__ float sW[32][64];   // [k][col]
    int t  = threadIdx.x;
    int br = blockIdx.x * 64;
    int tx = t & 15, ty = t >> 4;
    float acc[4][4] = {};

    for (int kc = 0; kc < K; kc += 32) {
        #pragma unroll
        for (int i = 0; i < 8; i++) {
            int e2 = t + i * 256;
            int r = e2 >> 5, kk = e2 & 31;
            int row = br + r;
            float v = 0.f;
            if (row < NN) {
                v = X[row * K + kc + kk];
                if (IN_RELU) v = fmaxf(v + inb[kc + kk], 0.f);
            }
            sX[kk][r] = v;
        }
        #pragma unroll
        for (int i = 0; i < 8; i++) {
            int e2 = t + i * 256;
            int c = e2 & 63, kk = e2 >> 6;
            sW[kk][c] = W[(kc + kk) * 64 + c];
        }
        __syncthreads();
        #pragma unroll
        for (int kk = 0; kk < 32; kk++) {
            float a[4], b[4];
            #pragma unroll
            for (int i2 = 0; i2 < 4; i2++) a[i2] = sX[kk][ty * 4 + i2];
            #pragma unroll
            for (int j = 0; j < 4; j++) b[j] = sW[kk][tx * 4 + j];
            #pragma unroll
            for (int i2 = 0; i2 < 4; i2++)
                #pragma unroll
                for (int j = 0; j < 4; j++)
                    acc[i2][j] += a[i2] * b[j];
        }
        __syncthreads();
    }
    #pragma unroll
    for (int i2 = 0; i2 < 4; i2++) {
        int row = br + ty * 4 + i2;
        if (row < NN) {
            if (OUT_NORM) {
                float d = dinv[row];
                float4 hn = make_float4(acc[i2][0] * d, acc[i2][1] * d,
                                        acc[i2][2] * d, acc[i2][3] * d);
                *(float4*)&OutA[row * HID + tx * 4] = hn;   // Hn
                float4 a2 = make_float4(hn.x * d, hn.y * d, hn.z * d, hn.w * d);
                *(float4*)&OutB[row * HID + tx * 4] = a2;   // Acc (self term)
            } else {
                float4 v = make_float4(acc[i2][0], acc[i2][1], acc[i2][2], acc[i2][3]);
                *(float4*)&OutA[row * ldA + colOff + tx * 4] = v;
            }
        }
    }
}

// ---------------- edge scatter: Acc[dst] += Hn[src] * dinv[dst] -------------
__global__ void k_scatter(const float* __restrict__ Hn, const float* __restrict__ dinv,
                          const int* __restrict__ ei, float* __restrict__ Acc) {
    int tid = blockIdx.x * blockDim.x + threadIdx.x;
    if (tid >= NE * 16) return;
    int e = tid >> 4, q = tid & 15;
    int src = ei[e];
    int dst = ei[NE + e];
    float n = dinv[dst];
    float4 v = *(const float4*)&Hn[src * HID + q * 4];
    v.x *= n; v.y *= n; v.z *= n; v.w *= n;
    red_add_v4(&Acc[dst * HID + q * 4], v);
}

// ---------------- edge MLP: half-warp per edge, 8 edges per half-warp -------
// Acc2 holds pre-activation layer2; relu(.+b2) is applied on the fly by the
// AB gemms, so AB already encodes final h. out = relu(A[s]+B[d]+attr@We+bm1)@Wm2+bm2
#define EMLP_BLOCKS 6250
__global__ void k_edge_mlp(const float* __restrict__ AB, const int* __restrict__ ei,
                           const float* __restrict__ attr, const float* __restrict__ Wm1,
                           const float* __restrict__ bm1, const float* __restrict__ Wm2,
                           const float* __restrict__ bm2, float* __restrict__ out) {
    __shared__ float sWe[EDIM][HID];   // Wm1 rows 128..143
    __shared__ float sW2[HID][2];
    __shared__ float sb1[HID];
    __shared__ float sb2[2];
    int t = threadIdx.x;
    const float* We = Wm1 + 128 * HID;
    for (int i = t; i < EDIM * HID; i += blockDim.x) ((float*)sWe)[i] = We[i];
    for (int i = t; i < HID * 2; i += blockDim.x)    ((float*)sW2)[i] = Wm2[i];
    if (t < HID) sb1[t] = bm1[t];
    if (t < 2)   sb2[t] = bm2[t];
    __syncthreads();

    const int HALVES = EMLP_BLOCKS * 256 / 16;       // 100000 half-warps
    int h = (blockIdx.x * blockDim.x + t) >> 4;      // half-warp id
    int l = t & 15;

    #pragma unroll
    for (int it = 0; it < 8; it++) {
        int e = h + it * HALVES;                     // coalesced across halves
        if (e < NE) {
            int src = ei[e];
            int dst = ei[NE + e];
            float4 a = *(const float4*)&AB[src * 128 + l * 4];
            float4 b = *(const float4*)&AB[dst * 128 + 64 + l * 4];
            float av = attr[e * EDIM + l];

            float s0 = 0.f, s1 = 0.f, s2 = 0.f, s3 = 0.f;
            #pragma unroll
            for (int k = 0; k < EDIM; k++) {
                float ak = __shfl_sync(0xffffffffu, av, k, 16);
                s0 += ak * sWe[k][l * 4 + 0];
                s1 += ak * sWe[k][l * 4 + 1];
                s2 += ak * sWe[k][l * 4 + 2];
                s3 += ak * sWe[k][l * 4 + 3];
            }
            int c = l * 4;
            float e0 = fmaxf(a.x + b.x + s0 + sb1[c + 0], 0.f);
            float e1 = fmaxf(a.y + b.y + s1 + sb1[c + 1], 0.f);
            float e2 = fmaxf(a.z + b.z + s2 + sb1[c + 2], 0.f);
            float e3 = fmaxf(a.w + b.w + s3 + sb1[c + 3], 0.f);

            float p0 = e0 * sW2[c][0] + e1 * sW2[c + 1][0]
                     + e2 * sW2[c + 2][0] + e3 * sW2[c + 3][0];
            float p1 = e0 * sW2[c][1] + e1 * sW2[c + 1][1]
                     + e2 * sW2[c + 2][1] + e3 * sW2[c + 3][1];
            #pragma unroll
            for (int off = 8; off; off >>= 1) {
                p0 += __shfl_xor_sync(0xffffffffu, p0, off, 16);
                p1 += __shfl_xor_sync(0xffffffffu, p1, off, 16);
            }
            if (l == 0) {
                float2 r = make_float2(p0 + sb2[0], p1 + sb2[1]);
                *(float2*)&out[e * 2] = r;
            }
        }
    }
}

// ---------------- launch ----------------------------------------------------
extern "C" void kernel_launch(void* const* d_in, const int* in_sizes, int n_in,
                              void* d_out, int out_size) {
    const float* x    = (const float*)d_in[0];
    const int*   ei   = (const int*)d_in[1];     // edge_index is int32 (JAX x64 off)
    const float* attr = (const float*)d_in[2];
    const float* W1   = (const float*)d_in[3];
    const float* b1   = (const float*)d_in[4];
    const float* W2   = (const float*)d_in[5];
    const float* b2   = (const float*)d_in[6];
    const float* Wm1  = (const float*)d_in[7];
    const float* bm1  = (const float*)d_in[8];
    const float* Wm2  = (const float*)d_in[9];
    const float* bm2  = (const float*)d_in[10];
    float* out = (float*)d_out;

    float *Hn, *Acc, *AB, *dinv; int* deg;
    cudaGetSymbolAddress((void**)&Hn,   g_Hn);
    cudaGetSymbolAddress((void**)&Acc,  g_Acc);
    cudaGetSymbolAddress((void**)&AB,   g_AB);
    cudaGetSymbolAddress((void**)&deg,  g_deg);
    cudaGetSymbolAddress((void**)&dinv, g_dinv);

    const int T = 256;
    int gb_nodes = (NN + T - 1) / T;
    int gb_edges = (NE + T - 1) / T;
    int gb_ev4   = (NE * 16 + T - 1) / T;
    int gb_gemm  = (NN + 63) / 64;

    // graph degrees (recomputed every call; deterministic)
    k_deg_init<<<gb_nodes, T>>>(deg);
    k_deg_count<<<gb_edges, T>>>(ei, deg);
    k_deg_inv<<<gb_nodes, T>>>(deg, dinv);

    // ---- GCN layer 1: Hn = (x@W1)*dinv, Acc = Hn*dinv; then scatter ----
    k_gemm64<NDIM, false, true><<<gb_gemm, T>>>(x, W1, nullptr, dinv, Hn, Acc, HID, 0);
    k_scatter<<<gb_ev4, T>>>(Hn, dinv, ei, Acc);

    // ---- GCN layer 2: input relu(Acc+b1) fused; in-place Acc update ----
    k_gemm64<HID, true, true><<<gb_gemm, T>>>(Acc, W2, b1, dinv, Hn, Acc, HID, 0);
    k_scatter<<<gb_ev4, T>>>(Hn, dinv, ei, Acc);

    // ---- per-node edge-MLP partials, input relu(Acc+b2) fused ----
    k_gemm64<HID, true, false><<<gb_gemm, T>>>(Acc, Wm1,           b2, nullptr, AB, nullptr, 128, 0);
    k_gemm64<HID, true, false><<<gb_gemm, T>>>(Acc, Wm1 + 64 * 64, b2, nullptr, AB, nullptr, 128, 64);

    // ---- edge MLP ----
    k_edge_mlp<<<EMLP_BLOCKS, T>>>(AB, ei, attr, Wm1, bm1, Wm2, bm2, out);
}

// round 10
// speedup vs baseline: 2.1183x; 1.0074x over previous
#include <cuda_runtime.h>

#define NN 50000
#define NE 800000
#define NDIM 128
#define HID 64
#define EDIM 16

// ---------------- scratch (device globals; no allocation allowed) ----------
__device__ __align__(16) float g_Hn[NN * HID];     // (X@W) * dinv[row]
__device__ __align__(16) float g_Acc[NN * HID];    // aggregation accumulator
__device__ __align__(16) float g_AB[NN * 128];     // [A | B] per node for edge MLP
__device__ int   g_deg[NN];
__device__ float g_dinv[NN];

// ---------------- vector reduction helper ----------------------------------
__device__ __forceinline__ void red_add_v4(float* p, float4 v) {
    asm volatile("red.global.add.v4.f32 [%0], {%1,%2,%3,%4};"
                 :: "l"(p), "f"(v.x), "f"(v.y), "f"(v.z), "f"(v.w)
                 : "memory");
}

// ---------------- degree kernels -------------------------------------------
__global__ void k_deg_init(int* deg) {
    int i = blockIdx.x * blockDim.x + threadIdx.x;
    if (i < NN) deg[i] = 1;   // self-loop
}
__global__ void k_deg_count(const int* __restrict__ ei, int* deg) {
    int e = blockIdx.x * blockDim.x + threadIdx.x;
    if (e < NE) atomicAdd(&deg[ei[NE + e]], 1);
}
__global__ void k_deg_inv(const int* __restrict__ deg, float* dinv) {
    int i = blockIdx.x * blockDim.x + threadIdx.x;
    if (i < NN) dinv[i] = rsqrtf((float)deg[i]);
}

// ---------------- GEMM: Out = [relu(X+b)] @ W[K,64] ------------------------
// 128x64 tile, 256 threads, 8x4 microtile, K chunked by 32.
// sX padded to 132 floats/row -> 16B-aligned rows, vectorized LDS.128 reads.
template <int K, bool IN_RELU, bool OUT_NORM>
__global__ void __launch_bounds__(256, 3)
k_gemm(const float* __restrict__ X, const float* __restrict__ W,
       const float* __restrict__ inb, const float* __restrict__ dinv,
       float* __restrict__ OutA, float* __restrict__ OutB,
       int ldA, int colOff) {
    __shared__ float sX[32][132];   // [k][row], 132*4B = 16B-aligned stride
    __shared__ float sW[32][64];    // [k][col]
    int t  = threadIdx.x;
    int br = blockIdx.x * 128;
    int tx = t & 15, ty = t >> 4;   // col group, row group
    float acc[8][4] = {};

    for (int kc = 0; kc < K; kc += 32) {
        // stage X tile (128 rows x 32 k), transposed into sX[k][row]
        #pragma unroll
        for (int i = 0; i < 4; i++) {
            int id = t + i * 256;
            int r  = id >> 3;          // 0..127
            int kb = (id & 7) * 4;     // k sub-chunk 0,4,..,28
            int row = br + r;
            float4 v = make_float4(0.f, 0.f, 0.f, 0.f);
            if (row < NN) {
                v = *(const float4*)&X[row * K + kc + kb];
                if (IN_RELU) {
                    v.x = fmaxf(v.x + inb[kc + kb + 0], 0.f);
                    v.y = fmaxf(v.y + inb[kc + kb + 1], 0.f);
                    v.z = fmaxf(v.z + inb[kc + kb + 2], 0.f);
                    v.w = fmaxf(v.w + inb[kc + kb + 3], 0.f);
                }
            }
            sX[kb + 0][r] = v.x;
            sX[kb + 1][r] = v.y;
            sX[kb + 2][r] = v.z;
            sX[kb + 3][r] = v.w;
        }
        // stage W tile (32 k x 64 cols)
        #pragma unroll
        for (int i = 0; i < 2; i++) {
            int id = t + i * 256;
            int kk = id >> 4, c4 = (id & 15) * 4;
            *(float4*)&sW[kk][c4] = *(const float4*)&W[(kc + kk) * 64 + c4];
        }
        __syncthreads();
        #pragma unroll
        for (int kk = 0; kk < 32; kk++) {
            float a[8], b[4];
            *(float4*)&a[0] = *(const float4*)&sX[kk][ty * 8];
            *(float4*)&a[4] = *(const float4*)&sX[kk][ty * 8 + 4];
            *(float4*)&b[0] = *(const float4*)&sW[kk][tx * 4];
            #pragma unroll
            for (int i2 = 0; i2 < 8; i2++)
                #pragma unroll
                for (int j = 0; j < 4; j++)
                    acc[i2][j] += a[i2] * b[j];
        }
        __syncthreads();
    }
    #pragma unroll
    for (int i2 = 0; i2 < 8; i2++) {
        int row = br + ty * 8 + i2;
        if (row < NN) {
            if (OUT_NORM) {
                float d = dinv[row];
                float4 hn = make_float4(acc[i2][0] * d, acc[i2][1] * d,
                                        acc[i2][2] * d, acc[i2][3] * d);
                *(float4*)&OutA[row * HID + tx * 4] = hn;   // Hn
                float4 a2 = make_float4(hn.x * d, hn.y * d, hn.z * d, hn.w * d);
                *(float4*)&OutB[row * HID + tx * 4] = a2;   // Acc (self term)
            } else {
                float4 v = make_float4(acc[i2][0], acc[i2][1], acc[i2][2], acc[i2][3]);
                *(float4*)&OutA[row * ldA + colOff + tx * 4] = v;
            }
        }
    }
}

// ---------------- edge scatter: Acc[dst] += Hn[src] * dinv[dst] -------------
__global__ void k_scatter(const float* __restrict__ Hn, const float* __restrict__ dinv,
                          const int* __restrict__ ei, float* __restrict__ Acc) {
    int tid = blockIdx.x * blockDim.x + threadIdx.x;
    if (tid >= NE * 16) return;
    int e = tid >> 4, q = tid & 15;
    int src = ei[e];
    int dst = ei[NE + e];
    float n = dinv[dst];
    float4 v = *(const float4*)&Hn[src * HID + q * 4];
    v.x *= n; v.y *= n; v.z *= n; v.w *= n;
    red_add_v4(&Acc[dst * HID + q * 4], v);
}

// ---------------- edge MLP: half-warp per edge, 8 edges per half-warp -------
#define EMLP_BLOCKS 6250
__global__ void k_edge_mlp(const float* __restrict__ AB, const int* __restrict__ ei,
                           const float* __restrict__ attr, const float* __restrict__ Wm1,
                           const float* __restrict__ bm1, const float* __restrict__ Wm2,
                           const float* __restrict__ bm2, float* __restrict__ out) {
    __shared__ float sWe[EDIM][HID];   // Wm1 rows 128..143
    __shared__ float sW2[HID][2];
    __shared__ float sb1[HID];
    __shared__ float sb2[2];
    int t = threadIdx.x;
    const float* We = Wm1 + 128 * HID;
    for (int i = t; i < EDIM * HID; i += blockDim.x) ((float*)sWe)[i] = We[i];
    for (int i = t; i < HID * 2; i += blockDim.x)    ((float*)sW2)[i] = Wm2[i];
    if (t < HID) sb1[t] = bm1[t];
    if (t < 2)   sb2[t] = bm2[t];
    __syncthreads();

    const int HALVES = EMLP_BLOCKS * 256 / 16;       // 100000 half-warps
    int h = (blockIdx.x * blockDim.x + t) >> 4;      // half-warp id
    int l = t & 15;

    #pragma unroll
    for (int it = 0; it < 8; it++) {
        int e = h + it * HALVES;                     // coalesced across halves
        if (e < NE) {
            int src = ei[e];
            int dst = ei[NE + e];
            float4 a = *(const float4*)&AB[src * 128 + l * 4];
            float4 b = *(const float4*)&AB[dst * 128 + 64 + l * 4];
            float av = attr[e * EDIM + l];

            float s0 = 0.f, s1 = 0.f, s2 = 0.f, s3 = 0.f;
            #pragma unroll
            for (int k = 0; k < EDIM; k++) {
                float ak = __shfl_sync(0xffffffffu, av, k, 16);
                s0 += ak * sWe[k][l * 4 + 0];
                s1 += ak * sWe[k][l * 4 + 1];
                s2 += ak * sWe[k][l * 4 + 2];
                s3 += ak * sWe[k][l * 4 + 3];
            }
            int c = l * 4;
            float e0 = fmaxf(a.x + b.x + s0 + sb1[c + 0], 0.f);
            float e1 = fmaxf(a.y + b.y + s1 + sb1[c + 1], 0.f);
            float e2 = fmaxf(a.z + b.z + s2 + sb1[c + 2], 0.f);
            float e3 = fmaxf(a.w + b.w + s3 + sb1[c + 3], 0.f);

            float p0 = e0 * sW2[c][0] + e1 * sW2[c + 1][0]
                     + e2 * sW2[c + 2][0] + e3 * sW2[c + 3][0];
            float p1 = e0 * sW2[c][1] + e1 * sW2[c + 1][1]
                     + e2 * sW2[c + 2][1] + e3 * sW2[c + 3][1];
            #pragma unroll
            for (int off = 8; off; off >>= 1) {
                p0 += __shfl_xor_sync(0xffffffffu, p0, off, 16);
                p1 += __shfl_xor_sync(0xffffffffu, p1, off, 16);
            }
            if (l == 0) {
                float2 r = make_float2(p0 + sb2[0], p1 + sb2[1]);
                *(float2*)&out[e * 2] = r;
            }
        }
    }
}

// ---------------- launch ----------------------------------------------------
extern "C" void kernel_launch(void* const* d_in, const int* in_sizes, int n_in,
                              void* d_out, int out_size) {
    const float* x    = (const float*)d_in[0];
    const int*   ei   = (const int*)d_in[1];     // edge_index is int32 (JAX x64 off)
    const float* attr = (const float*)d_in[2];
    const float* W1   = (const float*)d_in[3];
    const float* b1   = (const float*)d_in[4];
    const float* W2   = (const float*)d_in[5];
    const float* b2   = (const float*)d_in[6];
    const float* Wm1  = (const float*)d_in[7];
    const float* bm1  = (const float*)d_in[8];
    const float* Wm2  = (const float*)d_in[9];
    const float* bm2  = (const float*)d_in[10];
    float* out = (float*)d_out;

    float *Hn, *Acc, *AB, *dinv; int* deg;
    cudaGetSymbolAddress((void**)&Hn,   g_Hn);
    cudaGetSymbolAddress((void**)&Acc,  g_Acc);
    cudaGetSymbolAddress((void**)&AB,   g_AB);
    cudaGetSymbolAddress((void**)&deg,  g_deg);
    cudaGetSymbolAddress((void**)&dinv, g_dinv);

    const int T = 256;
    int gb_nodes = (NN + T - 1) / T;
    int gb_edges = (NE + T - 1) / T;
    int gb_ev4   = (NE * 16 + T - 1) / T;
    int gb_gemm  = (NN + 127) / 128;

    // graph degrees (recomputed every call; deterministic)
    k_deg_init<<<gb_nodes, T>>>(deg);
    k_deg_count<<<gb_edges, T>>>(ei, deg);
    k_deg_inv<<<gb_nodes, T>>>(deg, dinv);

    // ---- GCN layer 1: Hn = (x@W1)*dinv, Acc = Hn*dinv; then scatter ----
    k_gemm<NDIM, false, true><<<gb_gemm, T>>>(x, W1, nullptr, dinv, Hn, Acc, HID, 0);
    k_scatter<<<gb_ev4, T>>>(Hn, dinv, ei, Acc);

    // ---- GCN layer 2: input relu(Acc+b1) fused; in-place Acc update ----
    k_gemm<HID, true, true><<<gb_gemm, T>>>(Acc, W2, b1, dinv, Hn, Acc, HID, 0);
    k_scatter<<<gb_ev4, T>>>(Hn, dinv, ei, Acc);

    // ---- per-node edge-MLP partials, input relu(Acc+b2) fused ----
    k_gemm<HID, true, false><<<gb_gemm, T>>>(Acc, Wm1,           b2, nullptr, AB, nullptr, 128, 0);
    k_gemm<HID, true, false><<<gb_gemm, T>>>(Acc, Wm1 + 64 * 64, b2, nullptr, AB, nullptr, 128, 64);

    // ---- edge MLP ----
    k_edge_mlp<<<EMLP_BLOCKS, T>>>(AB, ei, attr, Wm1, bm1, Wm2, bm2, out);
}